// round 1
// baseline (speedup 1.0000x reference)
#include <cuda_runtime.h>
#include <cuda_bf16.h>
#include <cstdint>

#define KDIM 256
#define ODIM 64
#define MAX_NODES 50048

// Scratch for support = features @ weight  (static __device__ — no allocation)
__device__ float g_support[(size_t)MAX_NODES * ODIM];

// ---------------------------------------------------------------------------
// GEMM: support[n, 64] = features[n, 256] @ weight[256, 64]
// Block: 256 threads, computes a 64-row x 64-col tile.
// Weight staged through static smem in two 128-K chunks (32 KB).
// Thread (tx = tid%16 -> 4 cols, ty = tid/16 -> 4 rows), 4x4 register tile.
// ---------------------------------------------------------------------------
__global__ void gnn_gemm_kernel(const float* __restrict__ F,
                                const float* __restrict__ W,
                                int nrows) {
    __shared__ float sw[128 * ODIM];  // 32 KB

    const int tid = threadIdx.x;
    const int tx = tid & 15;   // col group: cols [tx*4, tx*4+4)
    const int ty = tid >> 4;   // row group: rows [row0, row0+4)
    const int row0 = blockIdx.x * 64 + ty * 4;
    const int c0 = tx * 4;

    float4 acc[4];
#pragma unroll
    for (int r = 0; r < 4; ++r) acc[r] = make_float4(0.f, 0.f, 0.f, 0.f);

    // clamp rows for loads (only the last block has a tail); stores are guarded
    int rowc[4];
#pragma unroll
    for (int r = 0; r < 4; ++r) {
        int rr = row0 + r;
        rowc[r] = rr < nrows ? rr : (nrows - 1);
    }

    for (int pass = 0; pass < 2; ++pass) {
        // cooperative load of weight chunk [128 x 64] into smem (float4, coalesced)
        const float4* wsrc = reinterpret_cast<const float4*>(W + pass * 128 * ODIM);
        float4* wdst = reinterpret_cast<float4*>(sw);
#pragma unroll
        for (int i = tid; i < 128 * ODIM / 4; i += 256) wdst[i] = wsrc[i];
        __syncthreads();

        const int kbase = pass * 128;
#pragma unroll 4
        for (int kk = 0; kk < 128; kk += 4) {
            float4 f[4];
#pragma unroll
            for (int r = 0; r < 4; ++r)
                f[r] = *reinterpret_cast<const float4*>(
                    F + (size_t)rowc[r] * KDIM + kbase + kk);
#pragma unroll
            for (int u = 0; u < 4; ++u) {
                float4 w4 = *reinterpret_cast<const float4*>(sw + (kk + u) * ODIM + c0);
#pragma unroll
                for (int r = 0; r < 4; ++r) {
                    float fv = (u == 0) ? f[r].x : (u == 1) ? f[r].y
                             : (u == 2) ? f[r].z : f[r].w;
                    acc[r].x += fv * w4.x;
                    acc[r].y += fv * w4.y;
                    acc[r].z += fv * w4.z;
                    acc[r].w += fv * w4.w;
                }
            }
        }
        __syncthreads();
    }

#pragma unroll
    for (int r = 0; r < 4; ++r) {
        int rr = row0 + r;
        if (rr < nrows)
            *reinterpret_cast<float4*>(g_support + (size_t)rr * ODIM + c0) = acc[r];
    }
}

// ---------------------------------------------------------------------------
// Scatter SpMM: out[row] += support[col] * w  for each edge.
// 16 threads per edge; each thread handles 4 contiguous columns via float4
// gather + red.global.add.v4.f32 (one vector reduction per 16 B).
// ---------------------------------------------------------------------------
__global__ void gnn_scatter_kernel(const int* __restrict__ erow,
                                   const int* __restrict__ ecol,
                                   const float* __restrict__ ew,
                                   float* __restrict__ out,
                                   int E) {
    int gid = blockIdx.x * blockDim.x + threadIdx.x;
    int e = gid >> 4;
    if (e >= E) return;
    int j = (gid & 15) * 4;

    int r = erow[e];
    int c = ecol[e];
    float w = ew[e];

    float4 v = *reinterpret_cast<const float4*>(g_support + (size_t)c * ODIM + j);
    v.x *= w; v.y *= w; v.z *= w; v.w *= w;

    float* p = out + (size_t)r * ODIM + j;
    asm volatile("red.global.add.v4.f32 [%0], {%1, %2, %3, %4};"
                 :: "l"(p), "f"(v.x), "f"(v.y), "f"(v.z), "f"(v.w)
                 : "memory");
}

// ---------------------------------------------------------------------------
// Epilogue: out = tanh(out) if *active (device-side branch, deterministic)
// ---------------------------------------------------------------------------
__global__ void gnn_tanh_kernel(float* __restrict__ out,
                                const int* __restrict__ act,
                                int n) {
    int i = blockIdx.x * blockDim.x + threadIdx.x;
    if (i < n) {
        if (*act) out[i] = tanhf(out[i]);
    }
}

extern "C" void kernel_launch(void* const* d_in, const int* in_sizes, int n_in,
                              void* d_out, int out_size) {
    const float* F   = (const float*)d_in[0];   // features [N, 256]
    const float* W   = (const float*)d_in[1];   // weight   [256, 64]
    const int*   er  = (const int*)d_in[2];     // edge_row [E]
    const int*   ec  = (const int*)d_in[3];     // edge_col [E]
    const float* ew  = (const float*)d_in[4];   // edge_weight [E]
    const int*   act = (const int*)d_in[5];     // active flag

    int nrows = in_sizes[0] / KDIM;
    int E = in_sizes[2];
    float* out = (float*)d_out;

    // 1) dense projection into scratch
    gnn_gemm_kernel<<<(nrows + 63) / 64, 256>>>(F, W, nrows);

    // 2) zero the (poisoned) output
    cudaMemsetAsync(d_out, 0, (size_t)out_size * sizeof(float), 0);

    // 3) edge scatter-add (16 threads / edge)
    long long total = (long long)E * 16;
    int blocks = (int)((total + 255) / 256);
    gnn_scatter_kernel<<<blocks, 256>>>(er, ec, ew, out, E);

    // 4) tanh epilogue
    gnn_tanh_kernel<<<(out_size + 255) / 256, 256>>>(out, act, out_size);
}

// round 2
// speedup vs baseline: 1.2868x; 1.2868x over previous
#include <cuda_runtime.h>
#include <cuda_bf16.h>
#include <cstdint>

#define KDIM 256
#define ODIM 64
#define MAX_NODES 50048
#define SW_STRIDE 72  // 64 + 8 pad: bank = (k*8 + n) % 32 -> conflict-free B LDS

// Scratch for support = features @ weight  (static __device__ — no allocation)
__device__ float g_support[(size_t)MAX_NODES * ODIM];

__device__ __forceinline__ uint32_t f2tf32(float x) {
    uint32_t r;
    asm("cvt.rna.tf32.f32 %0, %1;" : "=r"(r) : "f"(x));
    return r;
}

// ---------------------------------------------------------------------------
// tf32 tensor-core GEMM: support[n,64] = F[n,256] @ W[256,64]
// Block: 256 threads (8 warps), tile 128 rows x 64 cols.
// Warp w -> rows [w*16, w*16+16), all 64 cols: 8 accumulator n-tiles of m16n8.
// W staged through smem (two 128-K passes, 36 KB, tf32, stride 72).
// ---------------------------------------------------------------------------
__global__ __launch_bounds__(256) void gnn_gemm_tf32(const float* __restrict__ F,
                                                     const float* __restrict__ W,
                                                     int nrows) {
    __shared__ uint32_t sw[128 * SW_STRIDE];  // 36 KB

    const int tid  = threadIdx.x;
    const int warp = tid >> 5;
    const int lane = tid & 31;
    const int g    = lane >> 2;   // group id 0..7
    const int tig  = lane & 3;    // thread-in-group 0..3

    const int rowbase = blockIdx.x * 128 + warp * 16;
    const int r0 = rowbase + g;
    const int r1 = rowbase + g + 8;
    const int r0c = r0 < nrows ? r0 : nrows - 1;
    const int r1c = r1 < nrows ? r1 : nrows - 1;
    const float* F0 = F + (size_t)r0c * KDIM;
    const float* F1 = F + (size_t)r1c * KDIM;

    float acc[8][4];
#pragma unroll
    for (int nt = 0; nt < 8; ++nt)
#pragma unroll
        for (int i = 0; i < 4; ++i) acc[nt][i] = 0.f;

    for (int pass = 0; pass < 2; ++pass) {
        // Cooperative load of W chunk [128 x 64] -> smem tf32, padded stride.
        const float4* src = reinterpret_cast<const float4*>(W + pass * 128 * ODIM);
#pragma unroll
        for (int i = tid; i < 128 * 16; i += 256) {
            float4 v = src[i];
            int krow = i >> 4;
            int nc = (i & 15) * 4;
            uint32_t* d = &sw[krow * SW_STRIDE + nc];
            d[0] = f2tf32(v.x);
            d[1] = f2tf32(v.y);
            d[2] = f2tf32(v.z);
            d[3] = f2tf32(v.w);
        }
        __syncthreads();

        const int kglob = pass * 128;
#pragma unroll 4
        for (int ks = 0; ks < 128; ks += 8) {
            uint32_t a0 = f2tf32(F0[kglob + ks + tig]);
            uint32_t a1 = f2tf32(F1[kglob + ks + tig]);
            uint32_t a2 = f2tf32(F0[kglob + ks + tig + 4]);
            uint32_t a3 = f2tf32(F1[kglob + ks + tig + 4]);
#pragma unroll
            for (int nt = 0; nt < 8; ++nt) {
                uint32_t b0 = sw[(ks + tig) * SW_STRIDE + nt * 8 + g];
                uint32_t b1 = sw[(ks + tig + 4) * SW_STRIDE + nt * 8 + g];
                asm("mma.sync.aligned.m16n8k8.row.col.f32.tf32.tf32.f32 "
                    "{%0,%1,%2,%3}, {%4,%5,%6,%7}, {%8,%9}, {%0,%1,%2,%3};"
                    : "+f"(acc[nt][0]), "+f"(acc[nt][1]),
                      "+f"(acc[nt][2]), "+f"(acc[nt][3])
                    : "r"(a0), "r"(a1), "r"(a2), "r"(a3), "r"(b0), "r"(b1));
            }
        }
        __syncthreads();
    }

    // Store: c0/c1 -> row r0, cols tig*2, tig*2+1; c2/c3 -> row r1.
    if (r0 < nrows) {
        float* dst = g_support + (size_t)r0 * ODIM;
#pragma unroll
        for (int nt = 0; nt < 8; ++nt)
            *reinterpret_cast<float2*>(dst + nt * 8 + tig * 2) =
                make_float2(acc[nt][0], acc[nt][1]);
    }
    if (r1 < nrows) {
        float* dst = g_support + (size_t)r1 * ODIM;
#pragma unroll
        for (int nt = 0; nt < 8; ++nt)
            *reinterpret_cast<float2*>(dst + nt * 8 + tig * 2) =
                make_float2(acc[nt][2], acc[nt][3]);
    }
}

// ---------------------------------------------------------------------------
// Scatter SpMM: out[row] += support[col] * w   (16 threads / edge, float4 +
// red.global.add.v4.f32 — one vector reduction per 16 B).
// ---------------------------------------------------------------------------
__global__ void gnn_scatter_kernel(const int* __restrict__ erow,
                                   const int* __restrict__ ecol,
                                   const float* __restrict__ ew,
                                   float* __restrict__ out,
                                   int E) {
    int gid = blockIdx.x * blockDim.x + threadIdx.x;
    int e = gid >> 4;
    if (e >= E) return;
    int j = (gid & 15) * 4;

    int r = erow[e];
    int c = ecol[e];
    float w = ew[e];

    float4 v = *reinterpret_cast<const float4*>(g_support + (size_t)c * ODIM + j);
    v.x *= w; v.y *= w; v.z *= w; v.w *= w;

    float* p = out + (size_t)r * ODIM + j;
    asm volatile("red.global.add.v4.f32 [%0], {%1, %2, %3, %4};"
                 :: "l"(p), "f"(v.x), "f"(v.y), "f"(v.z), "f"(v.w)
                 : "memory");
}

// ---------------------------------------------------------------------------
// Epilogue: out = tanh(out) if *active (device-side branch, deterministic)
// ---------------------------------------------------------------------------
__global__ void gnn_tanh_kernel(float4* __restrict__ out,
                                const int* __restrict__ act,
                                int n4) {
    int i = blockIdx.x * blockDim.x + threadIdx.x;
    if (i < n4) {
        if (*act) {
            float4 v = out[i];
            v.x = tanhf(v.x); v.y = tanhf(v.y);
            v.z = tanhf(v.z); v.w = tanhf(v.w);
            out[i] = v;
        }
    }
}

extern "C" void kernel_launch(void* const* d_in, const int* in_sizes, int n_in,
                              void* d_out, int out_size) {
    const float* F   = (const float*)d_in[0];   // features [N, 256]
    const float* W   = (const float*)d_in[1];   // weight   [256, 64]
    const int*   er  = (const int*)d_in[2];     // edge_row [E]
    const int*   ec  = (const int*)d_in[3];     // edge_col [E]
    const float* ew  = (const float*)d_in[4];   // edge_weight [E]
    const int*   act = (const int*)d_in[5];     // active flag

    int nrows = in_sizes[0] / KDIM;
    int E = in_sizes[2];
    float* out = (float*)d_out;

    // 1) dense projection into scratch (tf32 tensor cores)
    gnn_gemm_tf32<<<(nrows + 127) / 128, 256>>>(F, W, nrows);

    // 2) zero the (poisoned) output
    cudaMemsetAsync(d_out, 0, (size_t)out_size * sizeof(float), 0);

    // 3) edge scatter-add (16 threads / edge)
    long long total = (long long)E * 16;
    int blocks = (int)((total + 255) / 256);
    gnn_scatter_kernel<<<blocks, 256>>>(er, ec, ew, out, E);

    // 4) tanh epilogue
    int n4 = out_size / 4;
    gnn_tanh_kernel<<<(n4 + 255) / 256, 256>>>((float4*)out, act, n4);
}